// round 2
// baseline (speedup 1.0000x reference)
#include <cuda_runtime.h>

#define NUM_BUCKETS 9311
#define D4 16   // 64 channels / 4 floats per float4
#define L 8     // categories per (b,c)

__global__ void __launch_bounds__(256)
enc_kernel(const int* __restrict__ x,
           const float4* __restrict__ table,
           float4* __restrict__ out,
           int n_rows) {
    int warp = (blockIdx.x * blockDim.x + threadIdx.x) >> 5;
    int lane = threadIdx.x & 31;
    int half = lane >> 4;      // which of the 2 rows this warp handles
    int sub  = lane & 15;      // float4 slot within the 64-channel row

    long long row = (long long)warp * 2 + half;
    bool valid = (row < n_rows);
    long long srow = valid ? row : (long long)(n_rows - 1);  // clamp so all lanes stay active

    // Lanes sub<8 each load one index, relu + hash + mask, pack into one int.
    int packed = 0;
    if (sub < L) {
        int v = x[srow * L + sub];
        if (v < 0) v = 0;
        int h = v % NUM_BUCKETS;
        packed = (h << 1) | (v > 0 ? 1 : 0);
    }
    int base = half << 4;

    float4 acc = make_float4(0.f, 0.f, 0.f, 0.f);
    int cnt = 0;
    #pragma unroll
    for (int j = 0; j < L; j++) {
        int p = __shfl_sync(0xffffffffu, packed, base + j);
        if (p & 1) {                              // uniform within the half-warp
            float4 e = __ldg(&table[(p >> 1) * D4 + sub]);
            acc.x += e.x; acc.y += e.y; acc.z += e.z; acc.w += e.w;
            cnt++;
        }
    }
    float inv = 1.0f / (float)(cnt > 0 ? cnt : 1);
    acc.x *= inv; acc.y *= inv; acc.z *= inv; acc.w *= inv;

    if (valid) out[row * D4 + sub] = acc;
}

extern "C" void kernel_launch(void* const* d_in, const int* in_sizes, int n_in,
                              void* d_out, int out_size) {
    const int*    x     = (const int*)d_in[0];
    const float4* table = (const float4*)d_in[1];
    float4*       out   = (float4*)d_out;

    int n_rows = in_sizes[0] / L;        // B*C = 262144
    int threads = 256;                   // 8 warps -> 16 rows per block
    int rows_per_block = (threads / 32) * 2;
    int blocks = (n_rows + rows_per_block - 1) / rows_per_block;

    enc_kernel<<<blocks, threads>>>(x, table, out, n_rows);
}

// round 3
// speedup vs baseline: 1.0315x; 1.0315x over previous
#include <cuda_runtime.h>

#define NUM_BUCKETS 9311
#define D4 16   // 64 channels / 4 floats per float4

__device__ __forceinline__ unsigned long long addx2(unsigned long long a, unsigned long long b) {
    unsigned long long r;
    asm("add.rn.f32x2 %0, %1, %2;" : "=l"(r) : "l"(a), "l"(b));
    return r;
}
__device__ __forceinline__ unsigned long long mulx2(unsigned long long a, unsigned long long b) {
    unsigned long long r;
    asm("mul.rn.f32x2 %0, %1, %2;" : "=l"(r) : "l"(a), "l"(b));
    return r;
}

union F4U {
    float4 f;
    unsigned long long u[2];
};

__global__ void __launch_bounds__(256)
enc_kernel(const int2* __restrict__ x2,
           const float4* __restrict__ table,
           float4* __restrict__ out,
           int n_rows) {
    int warp = (blockIdx.x * blockDim.x + threadIdx.x) >> 5;
    int lane = threadIdx.x & 31;
    int half = lane >> 4;      // which of the 2 rows this warp handles
    int sub  = lane & 15;      // float4 slot within the 64-channel row

    int row = warp * 2 + half;
    bool valid = (row < n_rows);
    int srow = valid ? row : (n_rows - 1);   // clamp: all lanes stay active for shfl

    // Lanes sub<4 each load 2 indices; pack two (hash<<1|mask) 15-bit codes per int.
    int packed = 0;
    if (sub < 4) {
        int2 v = x2[srow * 4 + sub];
        int a = max(v.x, 0);
        int b = max(v.y, 0);
        int ha = a % NUM_BUCKETS;
        int hb = b % NUM_BUCKETS;
        packed = ((ha << 1) | (a > 0 ? 1 : 0)) | ((((hb << 1) | (b > 0 ? 1 : 0))) << 16);
    }
    int base = half << 4;

    int p0 = __shfl_sync(0xffffffffu, packed, base + 0);
    int p1 = __shfl_sync(0xffffffffu, packed, base + 1);
    int p2 = __shfl_sync(0xffffffffu, packed, base + 2);
    int p3 = __shfl_sync(0xffffffffu, packed, base + 3);

    // Extract 8 hashes (bit31 of packed is always 0, >> is safe).
    int h0 = (p0 >> 1) & 0x7FFF, h1 = p0 >> 17;
    int h2 = (p1 >> 1) & 0x7FFF, h3 = p1 >> 17;
    int h4 = (p2 >> 1) & 0x7FFF, h5 = p2 >> 17;
    int h6 = (p3 >> 1) & 0x7FFF, h7 = p3 >> 17;

    // Count of x>0 via one popc (mask bits at positions 0,16 shifted apart).
    const int M = 0x00010001;
    int cnt = __popc((p0 & M) | ((p1 & M) << 2) | ((p2 & M) << 4) | ((p3 & M) << 6));

    // Unconditional gathers: table[0] is all zeros, so mask==0 entries (hash==0)
    // contribute nothing to the sum. All 8 loads batched for MLP.
    const float4* tab = table + sub;
    F4U e0, e1, e2, e3, e4, e5, e6, e7;
    e0.f = __ldg(tab + h0 * D4);
    e1.f = __ldg(tab + h1 * D4);
    e2.f = __ldg(tab + h2 * D4);
    e3.f = __ldg(tab + h3 * D4);
    e4.f = __ldg(tab + h4 * D4);
    e5.f = __ldg(tab + h5 * D4);
    e6.f = __ldg(tab + h6 * D4);
    e7.f = __ldg(tab + h7 * D4);

    // Packed f32x2 tree reduction: 2 lanes per instruction.
    unsigned long long s0a = addx2(e0.u[0], e1.u[0]), s0b = addx2(e0.u[1], e1.u[1]);
    unsigned long long s1a = addx2(e2.u[0], e3.u[0]), s1b = addx2(e2.u[1], e3.u[1]);
    unsigned long long s2a = addx2(e4.u[0], e5.u[0]), s2b = addx2(e4.u[1], e5.u[1]);
    unsigned long long s3a = addx2(e6.u[0], e7.u[0]), s3b = addx2(e6.u[1], e7.u[1]);
    unsigned long long t0a = addx2(s0a, s1a), t0b = addx2(s0b, s1b);
    unsigned long long t1a = addx2(s2a, s3a), t1b = addx2(s2b, s3b);
    unsigned long long ra  = addx2(t0a, t1a), rb  = addx2(t0b, t1b);

    float inv = 1.0f / (float)(cnt > 0 ? cnt : 1);
    unsigned int invb = __float_as_uint(inv);
    unsigned long long inv2 = ((unsigned long long)invb << 32) | invb;

    F4U res;
    res.u[0] = mulx2(ra, inv2);
    res.u[1] = mulx2(rb, inv2);

    if (valid) out[row * D4 + sub] = res.f;
}

extern "C" void kernel_launch(void* const* d_in, const int* in_sizes, int n_in,
                              void* d_out, int out_size) {
    const int2*   x2    = (const int2*)d_in[0];
    const float4* table = (const float4*)d_in[1];
    float4*       out   = (float4*)d_out;

    int n_rows = in_sizes[0] / 8;        // B*C = 262144
    int threads = 256;                   // 8 warps -> 16 rows per block
    int rows_per_block = (threads / 32) * 2;
    int blocks = (n_rows + rows_per_block - 1) / rows_per_block;

    enc_kernel<<<blocks, threads>>>(x2, table, out, n_rows);
}